// round 6
// baseline (speedup 1.0000x reference)
#include <cuda_runtime.h>
#include <math.h>

#define NB   36
#define NBP  37          // padded sT row stride: 37 mod 32 = 5, coprime -> conflict-free
#define SS   7
#define NOUT (2*NB + 2)  // 74

// One block per batch b, 256 threads. Thread t<252: (s=t/36, k=t%36).
// R4 skeleton (fully float4-vectorized staging incl. T via smem) +
//   (a) sT padded to stride 37 -> conflict-free matvec LDS
//   (b) matvec + warped STG moved to phase 1 (independent of ssum chain)
__global__ __launch_bounds__(256, 4)
void deepwarping_kernel(const float* __restrict__ ll1,   // [B,S,NB]
                        const float* __restrict__ ll2,   // [B,S,NB]
                        const float* __restrict__ inp,   // [B,S,NB]
                        const float* __restrict__ yaw,   // [B]
                        const float* __restrict__ T,     // [61,NB,NB]
                        const float* __restrict__ M,     // [NB,NB]
                        const float* __restrict__ pop,   // [2,NB]
                        float* __restrict__ out)         // [B,S,NOUT]
{
    const int b   = blockIdx.x;
    const int tid = threadIdx.x;

    __shared__ float seM [NB * NB];     // exp(M)
    __shared__ float sT  [NB * NBP];    // yaw-selected transform, padded rows
    __shared__ float se1 [SS * NB];     // exp(ll1)
    __shared__ float se2 [SS * NB];     // exp(ll2)
    __shared__ float si  [SS * NB];     // inp
    __shared__ float ssum[SS][NB];      // s_k
    __shared__ float spop[2 * NB];

    // yaw -> transform index (offset 30; rintf = round-half-even = jnp.round)
    const int idx  = 30 + (int)rintf(__ldg(yaw + b) * (180.0f / 3.14159265358979323846f));
    const int base = b * SS * NB;       // multiple of 4 -> float4-aligned

    // ---- staging, all LDGs float4 ----
    {   // exp(M): 324 float4
        const float4* M4 = (const float4*)M;
        #pragma unroll
        for (int t = tid; t < (NB * NB) / 4; t += 256) {
            float4 v = M4[t];
            ((float4*)seM)[t] = make_float4(__expf(v.x), __expf(v.y),
                                            __expf(v.z), __expf(v.w));
        }
    }
    {   // T[idx]: float4 LDG, scalar STS into padded rows
        const float4* T4 = (const float4*)(T + idx * NB * NB);
        #pragma unroll
        for (int t = tid; t < (NB * NB) / 4; t += 256) {
            const float4 v = T4[t];
            const int e = t * 4;
            const int r0 = e / NB,       c0 = e - r0 * NB;
            const int r1 = (e + 1) / NB, c1 = (e + 1) - r1 * NB;
            const int r2 = (e + 2) / NB, c2 = (e + 2) - r2 * NB;
            const int r3 = (e + 3) / NB, c3 = (e + 3) - r3 * NB;
            sT[r0 * NBP + c0] = v.x;
            sT[r1 * NBP + c1] = v.y;
            sT[r2 * NBP + c2] = v.z;
            sT[r3 * NBP + c3] = v.w;
        }
    }
    if (tid < (SS * NB) / 4) {          // 63 float4 per tensor
        float4 a = ((const float4*)(ll1 + base))[tid];
        float4 c = ((const float4*)(ll2 + base))[tid];
        float4 d = ((const float4*)(inp + base))[tid];
        ((float4*)se1)[tid] = make_float4(__expf(a.x), __expf(a.y), __expf(a.z), __expf(a.w));
        ((float4*)se2)[tid] = make_float4(__expf(c.x), __expf(c.y), __expf(c.z), __expf(c.w));
        ((float4*)si )[tid] = d;
    }
    if (tid >= 64 && tid < 64 + (2 * NB) / 4) {   // 18 float4, separate warp
        ((float4*)spop)[tid - 64] = ((const float4*)pop)[tid - 64];
    }
    __syncthreads();

    const int s  = tid / NB;            // valid when tid < 252
    const int k  = tid % NB;
    const int sb = s * NB;

    float acc = 0.0f;
    if (tid < SS * NB) {
        // --- warped[k] = sum_j sT[k][j]*si[s][j]  (conflict-free, independent chain) ---
        float w0 = 0.f, w1 = 0.f, w2 = 0.f, w3 = 0.f;
        const int kb = k * NBP;
        #pragma unroll
        for (int j = 0; j < NB; j += 4) {
            w0 += sT[kb + j    ] * si[sb + j    ];
            w1 += sT[kb + j + 1] * si[sb + j + 1];
            w2 += sT[kb + j + 2] * si[sb + j + 2];
            w3 += sT[kb + j + 3] * si[sb + j + 3];
        }

        // --- s_k = sum_i e1[i]*e2[(i+k)%36]*eM[i][(i+k)%36], 4 accumulators ---
        float a0 = 0.f, a1 = 0.f, a2 = 0.f, a3 = 0.f;
        #pragma unroll
        for (int i = 0; i < NB; i += 4) {
            int j0 = i + k;     if (j0 >= NB) j0 -= NB;
            int j1 = i + 1 + k; if (j1 >= NB) j1 -= NB;
            int j2 = i + 2 + k; if (j2 >= NB) j2 -= NB;
            int j3 = i + 3 + k; if (j3 >= NB) j3 -= NB;
            a0 += se1[sb + i    ] * (se2[sb + j0] * seM[(i    ) * NB + j0]);
            a1 += se1[sb + i + 1] * (se2[sb + j1] * seM[(i + 1) * NB + j1]);
            a2 += se1[sb + i + 2] * (se2[sb + j2] * seM[(i + 2) * NB + j2]);
            a3 += se1[sb + i + 3] * (se2[sb + j3] * seM[(i + 3) * NB + j3]);
        }
        acc = (a0 + a1) + (a2 + a3);
        ssum[s][k] = acc;

        // warped store: no barrier dependence, overlaps barrier-2 wait
        out[(b * SS + s) * NOUT + k] = (w0 + w1) + (w2 + w3);
    }
    __syncthreads();

    if (tid < SS * NB) {
        // tot: 4-way accumulator tree over broadcast LDS
        float t0 = 0.f, t1 = 0.f, t2 = 0.f, t3 = 0.f;
        #pragma unroll
        for (int kk = 0; kk < NB; kk += 4) {
            t0 += ssum[s][kk];
            t1 += ssum[s][kk + 1];
            t2 += ssum[s][kk + 2];
            t3 += ssum[s][kk + 3];
        }
        const float tot = (t0 + t1) + (t2 + t3);

        float* o = out + (b * SS + s) * NOUT;
        o[NB + 2 + k] = __logf(acc) - __logf(tot);

        if (k == 0) {
            const float inv = 1.0f / tot;
            float v0 = 0.f, v1 = 0.f;
            #pragma unroll
            for (int kk = 0; kk < NB; kk++) {
                const float p = ssum[s][kk] * inv;
                v0 += p * spop[kk];
                v1 += p * spop[NB + kk];
            }
            v0 += 1e-8f;
            const float n = sqrtf(v0 * v0 + v1 * v1);
            v0 /= n; v1 /= n;
            o[NB]     = fminf(fmaxf(v0, -1.0f), 1.0f);
            o[NB + 1] = fminf(fmaxf(v1, -1.0f), 1.0f);
        }
    }
}

extern "C" void kernel_launch(void* const* d_in, const int* in_sizes, int n_in,
                              void* d_out, int out_size)
{
    const float* ll1 = (const float*)d_in[0];   // loglikelihood1 [128,7,36]
    const float* ll2 = (const float*)d_in[1];   // loglikelihood2 [128,7,36]
    const float* inp = (const float*)d_in[2];   // inp            [128,7,36]
    const float* yaw = (const float*)d_in[3];   // yaw            [128]
    const float* T   = (const float*)d_in[4];   // transform_matrices [61,36,36]
    const float* M   = (const float*)d_in[5];   // logprior_rotate_matrix [36,36]
    // d_in[6] = template_log — equivalent to k=(j-i)%36 selector; unused
    const float* pop = (const float*)d_in[7];   // population_vector [2,36]
    float* out = (float*)d_out;

    const int B = in_sizes[3];                  // 128
    deepwarping_kernel<<<B, 256>>>(ll1, ll2, inp, yaw, T, M, pop, out);
}

// round 7
// speedup vs baseline: 1.0447x; 1.0447x over previous
#include <cuda_runtime.h>
#include <math.h>

#define NB   36
#define NB2  72
#define NBP  37          // padded sT row stride (conflict-free matvec)
#define SS   7
#define NOUT (2*NB + 2)  // 74

// One block per batch b, 256 threads. Thread t<252: (s=t/36, k=t%36).
// Key identity: logprior M is circulant-Toeplitz (M[i][j] = c[(j-i)%36]),
// so s_k = exp(c[k]) * circular-crosscorr(e1,e2)[k]. The 1296-entry exp(M)
// staging and per-iteration matrix LDS vanish.
__global__ __launch_bounds__(256, 4)
void deepwarping_kernel(const float* __restrict__ ll1,   // [B,S,NB]
                        const float* __restrict__ ll2,   // [B,S,NB]
                        const float* __restrict__ inp,   // [B,S,NB]
                        const float* __restrict__ yaw,   // [B]
                        const float* __restrict__ T,     // [61,NB,NB]
                        const float* __restrict__ M,     // [NB,NB]
                        const float* __restrict__ pop,   // [2,NB]
                        float* __restrict__ out)         // [B,S,NOUT]
{
    const int b   = blockIdx.x;
    const int tid = threadIdx.x;

    __shared__ float sT  [NB * NBP];    // yaw-selected transform, padded rows
    __shared__ float seMk[NB];          // exp(M[0][k]) = exp(c[k])
    __shared__ float se1 [SS * NB];     // exp(ll1)
    __shared__ float se2d[SS * NB2];    // exp(ll2), doubled rows [s][0..71]
    __shared__ float si  [SS * NB];     // inp
    __shared__ float ssum[SS][NB];      // s_k
    __shared__ float spop[2 * NB];

    // yaw -> transform index (offset 30; rintf = round-half-even = jnp.round)
    const int idx  = 30 + (int)rintf(__ldg(yaw + b) * (180.0f / 3.14159265358979323846f));
    const int base = b * SS * NB;       // multiple of 4 -> float4-aligned

    // ---- staging; disjoint warp groups so LDG/expf chains run in parallel ----
    {   // T[idx]: float4 LDG, scalar STS into padded rows (81 f4 over 256 thr)
        const float4* T4 = (const float4*)(T + idx * NB * NB);
        #pragma unroll
        for (int t = tid; t < (NB * NB) / 4; t += 256) {
            const float4 v = T4[t];
            const int e = t * 4;
            const int r0 = e / NB,       c0 = e - r0 * NB;
            const int r1 = (e + 1) / NB, c1 = (e + 1) - r1 * NB;
            const int r2 = (e + 2) / NB, c2 = (e + 2) - r2 * NB;
            const int r3 = (e + 3) / NB, c3 = (e + 3) - r3 * NB;
            sT[r0 * NBP + c0] = v.x;
            sT[r1 * NBP + c1] = v.y;
            sT[r2 * NBP + c2] = v.z;
            sT[r3 * NBP + c3] = v.w;
        }
    }
    if (tid < 63) {                      // exp(ll1)
        float4 a = ((const float4*)(ll1 + base))[tid];
        ((float4*)se1)[tid] = make_float4(__expf(a.x), __expf(a.y), __expf(a.z), __expf(a.w));
    } else if (tid < 128 && tid >= 64 && tid < 64 + 63) {   // exp(ll2), doubled
        const int t = tid - 64;          // 0..62 ; each s-row = 9 float4, no crossing
        float4 c = ((const float4*)(ll2 + base))[t];
        float4 e = make_float4(__expf(c.x), __expf(c.y), __expf(c.z), __expf(c.w));
        const int s = t / 9, q = t % 9;
        ((float4*)(se2d + s * NB2))[q]     = e;
        ((float4*)(se2d + s * NB2 + NB))[q] = e;
    } else if (tid >= 128 && tid < 128 + 63) {              // inp
        const int t = tid - 128;
        ((float4*)si)[t] = ((const float4*)(inp + base))[t];
    } else if (tid >= 192 && tid < 192 + 9) {               // exp(M row 0): 9 f4
        const int t = tid - 192;
        float4 m = ((const float4*)M)[t];
        ((float4*)seMk)[t] = make_float4(__expf(m.x), __expf(m.y), __expf(m.z), __expf(m.w));
    } else if (tid >= 208 && tid < 208 + 18) {              // pop: 18 f4
        const int t = tid - 208;
        ((float4*)spop)[t] = ((const float4*)pop)[t];
    }
    __syncthreads();

    const int s  = tid / NB;            // valid when tid < 252
    const int k  = tid % NB;
    const int sb = s * NB;
    const int sd = s * NB2 + k;         // doubled-row base, wrap-free

    float acc = 0.0f;
    if (tid < SS * NB) {
        // --- warped[k] = sum_j sT[k][j]*si[s][j]  (conflict-free, independent) ---
        float w0 = 0.f, w1 = 0.f, w2 = 0.f, w3 = 0.f;
        const int kb = k * NBP;
        #pragma unroll
        for (int j = 0; j < NB; j += 4) {
            w0 += sT[kb + j    ] * si[sb + j    ];
            w1 += sT[kb + j + 1] * si[sb + j + 1];
            w2 += sT[kb + j + 2] * si[sb + j + 2];
            w3 += sT[kb + j + 3] * si[sb + j + 3];
        }

        // --- s_k = eMk[k] * sum_i e1[i]*e2[i+k]  (no wrap, no matrix LDS) ---
        float a0 = 0.f, a1 = 0.f, a2 = 0.f, a3 = 0.f;
        #pragma unroll
        for (int i = 0; i < NB; i += 4) {
            a0 += se1[sb + i    ] * se2d[sd + i    ];
            a1 += se1[sb + i + 1] * se2d[sd + i + 1];
            a2 += se1[sb + i + 2] * se2d[sd + i + 2];
            a3 += se1[sb + i + 3] * se2d[sd + i + 3];
        }
        acc = ((a0 + a1) + (a2 + a3)) * seMk[k];
        ssum[s][k] = acc;

        // warped store: no barrier dependence, overlaps barrier-2 wait
        out[(b * SS + s) * NOUT + k] = (w0 + w1) + (w2 + w3);
    }
    __syncthreads();

    if (tid < SS * NB) {
        // tot: 4-way accumulator tree over broadcast LDS
        float t0 = 0.f, t1 = 0.f, t2 = 0.f, t3 = 0.f;
        #pragma unroll
        for (int kk = 0; kk < NB; kk += 4) {
            t0 += ssum[s][kk];
            t1 += ssum[s][kk + 1];
            t2 += ssum[s][kk + 2];
            t3 += ssum[s][kk + 3];
        }
        const float tot = (t0 + t1) + (t2 + t3);

        float* o = out + (b * SS + s) * NOUT;
        o[NB + 2 + k] = __logf(acc) - __logf(tot);

        if (k == 0) {
            const float inv = 1.0f / tot;
            float v0 = 0.f, v1 = 0.f;
            #pragma unroll
            for (int kk = 0; kk < NB; kk++) {
                const float p = ssum[s][kk] * inv;
                v0 += p * spop[kk];
                v1 += p * spop[NB + kk];
            }
            v0 += 1e-8f;
            const float n = sqrtf(v0 * v0 + v1 * v1);
            v0 /= n; v1 /= n;
            o[NB]     = fminf(fmaxf(v0, -1.0f), 1.0f);
            o[NB + 1] = fminf(fmaxf(v1, -1.0f), 1.0f);
        }
    }
}

extern "C" void kernel_launch(void* const* d_in, const int* in_sizes, int n_in,
                              void* d_out, int out_size)
{
    const float* ll1 = (const float*)d_in[0];   // loglikelihood1 [128,7,36]
    const float* ll2 = (const float*)d_in[1];   // loglikelihood2 [128,7,36]
    const float* inp = (const float*)d_in[2];   // inp            [128,7,36]
    const float* yaw = (const float*)d_in[3];   // yaw            [128]
    const float* T   = (const float*)d_in[4];   // transform_matrices [61,36,36]
    const float* M   = (const float*)d_in[5];   // logprior_rotate_matrix [36,36] (circulant)
    // d_in[6] = template_log — equivalent to k=(j-i)%36 selector; unused
    const float* pop = (const float*)d_in[7];   // population_vector [2,36]
    float* out = (float*)d_out;

    const int B = in_sizes[3];                  // 128
    deepwarping_kernel<<<B, 256>>>(ll1, ll2, inp, yaw, T, M, pop, out);
}